// round 17
// baseline (speedup 1.0000x reference)
#include <cuda_runtime.h>
#include <cuda_fp16.h>
#include <math.h>
#include <stdint.h>

#define DEPTH   12
#define BATCH   16
#define NTOK    256
#define TOKENS  (BATCH*NTOK)     /* 4096 */
#define DIM     768
#define HEADS   12
#define HD      64
#define HIDDEN  2048
#define EPSF    1e-5f
#define QS      2304             /* packed qkv row stride */
#define GUS     4096             /* packed g|u row stride */

/* ------------------------------------------------------------------ */
/* Scratch buffers                                                     */
/* ------------------------------------------------------------------ */
__device__ float  g_qkv[TOKENS*QS];
__device__ float  g_gu[TOKENS*GUS];
__device__ float  g_part[3*TOKENS*DIM];
__device__ __half g_yh_hi[TOKENS*DIM];
__device__ __half g_oh_hi[TOKENS*DIM];
__device__ __half g_mh_hi[TOKENS*HIDDEN];

/* packed split weights (B side keeps hi+lo) */
__device__ __half g_wqkv_hi[DEPTH*QS*DIM];
__device__ __half g_wqkv_lo[DEPTH*QS*DIM];
__device__ __half g_wo_hi[DEPTH*DIM*DIM];
__device__ __half g_wo_lo[DEPTH*DIM*DIM];
__device__ __half g_w1_hi[DEPTH*GUS*DIM];
__device__ __half g_w1_lo[DEPTH*GUS*DIM];
__device__ __half g_w2_hi[DEPTH*DIM*HIDDEN];
__device__ __half g_w2_lo[DEPTH*DIM*HIDDEN];
__device__ float  g_bqkv[DEPTH*QS];
__device__ float  g_b1[DEPTH*GUS];

/* ------------------------------------------------------------------ */
/* PTX helpers                                                         */
/* ------------------------------------------------------------------ */
__device__ __forceinline__ uint32_t smem_u32(const void* p) {
    uint32_t a;
    asm("{ .reg .u64 t; cvta.to.shared.u64 t, %1; cvt.u32.u64 %0, t; }"
        : "=r"(a) : "l"(p));
    return a;
}
__device__ __forceinline__ void cp16(uint32_t dst, const void* src) {
    asm volatile("cp.async.cg.shared.global [%0], [%1], 16;"
                 :: "r"(dst), "l"(src) : "memory");
}
__device__ __forceinline__ void cp_commit() {
    asm volatile("cp.async.commit_group;" ::: "memory");
}
template<int NWAIT>
__device__ __forceinline__ void cp_wait() {
    asm volatile("cp.async.wait_group %0;" :: "n"(NWAIT) : "memory");
}
template<int IMM>
__device__ __forceinline__ void ldmx4i(uint32_t& r0, uint32_t& r1,
                                       uint32_t& r2, uint32_t& r3, uint32_t a) {
    asm volatile("ldmatrix.sync.aligned.m8n8.x4.shared.b16 {%0,%1,%2,%3}, [%4+%5];"
                 : "=r"(r0), "=r"(r1), "=r"(r2), "=r"(r3) : "r"(a), "n"(IMM));
}
#define LDM4(f, base) do {                                        \
    ldmx4i<0>   ((f)[0][0], (f)[0][1], (f)[0][2], (f)[0][3], base); \
    ldmx4i<2048>((f)[1][0], (f)[1][1], (f)[1][2], (f)[1][3], base); \
    ldmx4i<4096>((f)[2][0], (f)[2][1], (f)[2][2], (f)[2][3], base); \
    ldmx4i<6144>((f)[3][0], (f)[3][1], (f)[3][2], (f)[3][3], base); \
} while (0)

__device__ __forceinline__ void mma16816(float* c, const uint32_t* a,
                                         uint32_t b0, uint32_t b1) {
    asm("mma.sync.aligned.m16n8k16.row.col.f32.f16.f16.f32 "
        "{%0,%1,%2,%3}, {%4,%5,%6,%7}, {%8,%9}, {%0,%1,%2,%3};"
        : "+f"(c[0]), "+f"(c[1]), "+f"(c[2]), "+f"(c[3])
        : "r"(a[0]), "r"(a[1]), "r"(a[2]), "r"(a[3]), "r"(b0), "r"(b1));
}
/* packed f32x2 ops (Blackwell family-wide PTX) */
typedef unsigned long long u64t;
__device__ __forceinline__ u64t fma2(u64t a, u64t b, u64t c) {
    u64t d;
    asm("fma.rn.f32x2 %0, %1, %2, %3;" : "=l"(d) : "l"(a), "l"(b), "l"(c));
    return d;
}
__device__ __forceinline__ u64t mul2(u64t a, u64t b) {
    u64t d;
    asm("mul.rn.f32x2 %0, %1, %2;" : "=l"(d) : "l"(a), "l"(b));
    return d;
}
__device__ __forceinline__ u64t pack2(float lo, float hi) {
    u64t d;
    asm("mov.b64 %0, {%1, %2};" : "=l"(d) : "f"(lo), "f"(hi));
    return d;
}
__device__ __forceinline__ float2 unpack2(u64t v) {
    float lo, hi;
    asm("mov.b64 {%0, %1}, %2;" : "=f"(lo), "=f"(hi) : "l"(v));
    return make_float2(lo, hi);
}

/* ------------------------------------------------------------------ */
/* 2-term split GEMM (NT): C = Ah*(Bhi + Blo)  (+bias)(+res)(+rope)    */
/* CTA tile 128x256, 8 warps of 64x64 (2x4), BK=64, double-buffered.   */
/* ------------------------------------------------------------------ */
#define PA 16384
#define PB 32768
#define BUFSZ (PA + 2*PB)              /* 81920 */
#define GEMM_SMEM (2*BUFSZ)            /* 163840 */

template<bool ROPE, bool PARTIAL>
__global__ void __launch_bounds__(256, 1) gemm_mma(
    const __half* __restrict__ Ah,
    const __half* __restrict__ Bhi, const __half* __restrict__ Blo,
    const float* __restrict__ bias, const float* __restrict__ res,
    float* __restrict__ C, const float* __restrict__ remb,
    int M, int N, int K) {
    extern __shared__ __align__(128) char smem[];
    uint32_t sb = smem_u32(smem);
    int tid = threadIdx.x, wid = tid >> 5, lane = tid & 31;
    int wm = wid >> 2, wn = wid & 3;
    int bm = blockIdx.y * 128, bn = blockIdx.x * 256;

    int l15 = lane & 15, kg = lane >> 4;
    uint32_t arow = (uint32_t)(wm * 64 + l15);
    uint32_t brow = (uint32_t)(wn * 64 + l15);
    int aswz = (int)(arow & 7), bswz = (int)(brow & 7);

    uint32_t aoff[4], boff[4];
    #pragma unroll
    for (int ks = 0; ks < 4; ks++) {
        int g = ks * 2 + kg;
        aoff[ks] = (uint32_t)((g ^ aswz) * 16);
        boff[ks] = (uint32_t)((g ^ bswz) * 16);
    }
    uint32_t aB0  = sb           + arow * 128u;
    uint32_t bHi0 = sb + PA      + brow * 128u;
    uint32_t bLo0 = sb + PA + PB + brow * 128u;

    float acc[4][8][4];
    #pragma unroll
    for (int i = 0; i < 4; i++)
        #pragma unroll
        for (int j = 0; j < 8; j++)
            #pragma unroll
            for (int e = 0; e < 4; e++) acc[i][j][e] = 0.f;

    int nch = K >> 6;
    int c0 = 0, c1 = nch;
    if (PARTIAL) {
        int z = blockIdx.z;
        c0 = (z * nch) / 3;
        c1 = ((z + 1) * nch) / 3;
    }

    auto load_chunk = [&](uint32_t dst, int ko) {
        #pragma unroll
        for (int j = 0; j < 4; j++) {
            int id = tid + j * 256;
            int row = id >> 3, g = id & 7;
            uint32_t off = (uint32_t)row * 128u + (uint32_t)((g ^ (row & 7)) * 16);
            size_t so = (size_t)(bm + row) * K + ko + g * 8;
            cp16(dst + off, Ah + so);
        }
        #pragma unroll
        for (int j = 0; j < 8; j++) {
            int id = tid + j * 256;
            int row = id >> 3, g = id & 7;
            uint32_t off = (uint32_t)row * 128u + (uint32_t)((g ^ (row & 7)) * 16);
            size_t so = (size_t)(bn + row) * K + ko + g * 8;
            cp16(dst + PA + off,      Bhi + so);
            cp16(dst + PA + PB + off, Blo + so);
        }
    };

    load_chunk(sb, c0 * 64);
    cp_commit();

    for (int c = c0; c < c1; c++) {
        if (c + 1 < c1) {
            load_chunk(sb + (uint32_t)(((c - c0 + 1) & 1) * BUFSZ), (c + 1) * 64);
            cp_commit();
            cp_wait<1>();
        } else {
            cp_wait<0>();
        }
        __syncthreads();

        uint32_t bofs = (uint32_t)(((c - c0) & 1) ? BUFSZ : 0);
        uint32_t a_b  = aB0  + bofs;
        uint32_t b_hi = bHi0 + bofs;
        uint32_t b_lo = bLo0 + bofs;

        #pragma unroll
        for (int ks = 0; ks < 4; ks++) {
            uint32_t afh[4][4], bfh[4][4];
            LDM4(afh, a_b  + aoff[ks]);
            LDM4(bfh, b_hi + boff[ks]);
            #pragma unroll
            for (int mf = 0; mf < 4; mf++)
                #pragma unroll
                for (int nf = 0; nf < 8; nf++)
                    mma16816(acc[mf][nf], afh[mf],
                             bfh[nf >> 1][nf & 1], bfh[nf >> 1][(nf & 1) + 2]);
            {
                uint32_t bfl[4][4];
                LDM4(bfl, b_lo + boff[ks]);
                #pragma unroll
                for (int mf = 0; mf < 4; mf++)
                    #pragma unroll
                    for (int nf = 0; nf < 8; nf++)
                        mma16816(acc[mf][nf], afh[mf],
                                 bfl[nf >> 1][nf & 1], bfl[nf >> 1][(nf & 1) + 2]);
            }
        }
        __syncthreads();
    }

    int r0 = lane >> 2, cb = (lane & 3) * 2;
    if (PARTIAL) {
        float* Cp = C + (size_t)blockIdx.z * M * N;
        #pragma unroll
        for (int mf = 0; mf < 4; mf++)
            #pragma unroll
            for (int nf = 0; nf < 8; nf++) {
                int n0 = bn + wn * 64 + nf * 8 + cb;
                #pragma unroll
                for (int half = 0; half < 2; half++) {
                    int m0 = bm + wm * 64 + mf * 16 + r0 + half * 8;
                    *(float2*)(Cp + (size_t)m0 * N + n0) =
                        make_float2(acc[mf][nf][half * 2], acc[mf][nf][half * 2 + 1]);
                }
            }
        return;
    }
    #pragma unroll
    for (int mf = 0; mf < 4; mf++) {
        #pragma unroll
        for (int nf = 0; nf < 8; nf++) {
            int n0 = bn + wn * 64 + nf * 8 + cb;
            float bz0 = bias ? bias[n0]     : 0.f;
            float bz1 = bias ? bias[n0 + 1] : 0.f;
            #pragma unroll
            for (int half = 0; half < 2; half++) {
                int m0 = bm + wm * 64 + mf * 16 + r0 + half * 8;
                float v0 = acc[mf][nf][half * 2]     + bz0;
                float v1 = acc[mf][nf][half * 2 + 1] + bz1;
                if (ROPE) {
                    if (n0 < 2*DIM) {
                        int pos = m0 & (NTOK - 1);
                        int d   = n0 & (HD - 1);
                        const float* e = remb + pos * (2*HD);
                        float2 sn = *(const float2*)(e + d);
                        float2 cs = *(const float2*)(e + HD + d);
                        float t0 = v0 * cs.x - v1 * sn.x;
                        float t1 = v1 * cs.y + v0 * sn.y;
                        v0 = t0; v1 = t1;
                    }
                }
                size_t idx = (size_t)m0 * N + n0;
                if (res) { v0 += res[idx]; v1 += res[idx + 1]; }
                *(float2*)(C + idx) = make_float2(v0, v1);
            }
        }
    }
}

/* ------------------------------------------------------------------ */
/* reduce3: h += bias + p0 + p1 + p2 (final layer only)                */
/* ------------------------------------------------------------------ */
__global__ void reduce3(float* __restrict__ h, const float* __restrict__ part,
                        const float* __restrict__ bias) {
    int i = blockIdx.x * blockDim.x + threadIdx.x;
    if (i >= TOKENS*DIM/4) return;
    float4 a  = ((const float4*)h)[i];
    float4 p0 = ((const float4*)part)[i];
    float4 p1 = ((const float4*)(part + TOKENS*DIM))[i];
    float4 p2 = ((const float4*)(part + 2*TOKENS*DIM))[i];
    float4 bz = *(const float4*)(bias + (i*4) % DIM);
    a.x += bz.x + ((p0.x + p1.x) + p2.x);
    a.y += bz.y + ((p0.y + p1.y) + p2.y);
    a.z += bz.z + ((p0.z + p1.z) + p2.z);
    a.w += bz.w + ((p0.w + p1.w) + p2.w);
    ((float4*)h)[i] = a;
}

/* ------------------------------------------------------------------ */
/* Single fused fp32 -> (hi, lo) split+pack for ALL weights            */
/* ------------------------------------------------------------------ */
struct CvtArgs {
    const float* src[7];
    __half* hi[7];
    __half* lo[7];
    int lr[7];
    int ltot[7];
    int off[7];
    int cum[8];
};
__device__ __forceinline__ void split2(float a, float b, __half2& h, __half2& l) {
    __half ha = __float2half_rn(a), hb = __float2half_rn(b);
    __half la = __float2half_rn(a - __half2float(ha));
    __half lb = __float2half_rn(b - __half2float(hb));
    h = __halves2half2(ha, hb);
    l = __halves2half2(la, lb);
}
__global__ void cvt_all(CvtArgs a, int total4) {
    int i4 = blockIdx.x * blockDim.x + threadIdx.x;
    if (i4 >= total4) return;
    int s = 0;
    #pragma unroll
    for (int j = 1; j < 7; j++) s += (i4 >= a.cum[j]);
    int i = (i4 - a.cum[s]) * 4;
    int l = i / a.lr[s];
    int rem = i - l * a.lr[s];
    size_t d = (size_t)l * a.ltot[s] + a.off[s] + rem;
    float4 v = *(const float4*)(a.src[s] + i);
    __half2 h0, l0, h1, l1;
    split2(v.x, v.y, h0, l0);
    split2(v.z, v.w, h1, l1);
    ((__half2*)(a.hi[s] + d))[0] = h0; ((__half2*)(a.hi[s] + d))[1] = h1;
    ((__half2*)(a.lo[s] + d))[0] = l0; ((__half2*)(a.lo[s] + d))[1] = l1;
}

/* ------------------------------------------------------------------ */
/* add_pos + bias packing fused                                        */
/* ------------------------------------------------------------------ */
__global__ void add_pos_prep(const float* __restrict__ x,
                             const float* __restrict__ pos,
                             float* __restrict__ h,
                             const float* __restrict__ bq,
                             const float* __restrict__ bv,
                             float* __restrict__ bqkv,
                             const float* __restrict__ bg,
                             const float* __restrict__ bx,
                             float* __restrict__ b1) {
    int idx = blockIdx.x * blockDim.x + threadIdx.x;
    if (idx < TOKENS*DIM) h[idx] = x[idx] + pos[idx % (NTOK*DIM)];
    if (idx < DEPTH*QS) {
        int l = idx / QS, c = idx % QS;
        bqkv[idx] = c < DIM ? bq[l*DIM + c]
                  : (c < 2*DIM ? 0.f : bv[l*DIM + c - 2*DIM]);
    }
    if (idx < DEPTH*GUS) {
        int l = idx / GUS, c = idx % GUS;
        b1[idx] = c < HIDDEN ? bg[l*HIDDEN + c] : bx[l*HIDDEN + c - HIDDEN];
    }
}

__device__ __forceinline__ float block_reduce_max(float m) {
    __shared__ float redm[8];
    #pragma unroll
    for (int o = 16; o > 0; o >>= 1)
        m = fmaxf(m, __shfl_xor_sync(0xffffffffu, m, o));
    int w = threadIdx.x >> 5, l = threadIdx.x & 31;
    if (l == 0) redm[w] = m;
    __syncthreads();
    if (threadIdx.x < 32) {
        m = (l < 8) ? redm[l] : 0.f;
        #pragma unroll
        for (int o = 4; o > 0; o >>= 1)
            m = fmaxf(m, __shfl_xor_sync(0xffffffffu, m, o));
        if (l == 0) redm[0] = m;
    }
    __syncthreads();
    return redm[0];
}

__device__ __forceinline__ uint32_t pack_h2(float a, float b) {
    __half2 h = __floats2half2_rn(a, b);
    return *(uint32_t*)&h;
}

/* ------------------------------------------------------------------ */
/* Fused residual-reduce + LayerNorm over DIM — WARP PER TOKEN.        */
/* 8 tokens/block, lane handles 6 strided float4s, shfl-only reduce.   */
/* ------------------------------------------------------------------ */
__global__ void __launch_bounds__(256) ln_fused(
    float* __restrict__ h, const float* __restrict__ part,
    const float* __restrict__ gbias,
    const float* __restrict__ w, const float* __restrict__ b,
    __half* __restrict__ ohi) {
    int wid = threadIdx.x >> 5, lane = threadIdx.x & 31;
    int t = blockIdx.x * 8 + wid;
    size_t base4 = (size_t)t * (DIM/4);
    float4 v[6];
    float s = 0.f, s2 = 0.f;
    #pragma unroll
    for (int i = 0; i < 6; i++) {
        int c4 = lane + i * 32;
        float4 x = ((const float4*)h)[base4 + c4];
        if (part) {
            float4 p0 = ((const float4*)part)[base4 + c4];
            float4 p1 = ((const float4*)(part + TOKENS*DIM))[base4 + c4];
            float4 p2 = ((const float4*)(part + 2*TOKENS*DIM))[base4 + c4];
            float4 bz = ((const float4*)gbias)[c4];
            x.x += bz.x + ((p0.x + p1.x) + p2.x);
            x.y += bz.y + ((p0.y + p1.y) + p2.y);
            x.z += bz.z + ((p0.z + p1.z) + p2.z);
            x.w += bz.w + ((p0.w + p1.w) + p2.w);
            ((float4*)h)[base4 + c4] = x;
        }
        v[i] = x;
        s  += x.x + x.y + x.z + x.w;
        s2 += x.x*x.x + x.y*x.y + x.z*x.z + x.w*x.w;
    }
    #pragma unroll
    for (int o = 16; o > 0; o >>= 1) {
        s  += __shfl_xor_sync(0xffffffffu, s,  o);
        s2 += __shfl_xor_sync(0xffffffffu, s2, o);
    }
    float mean = s / DIM;
    float var  = s2 / DIM - mean * mean;
    float inv  = rsqrtf(var + EPSF);
    #pragma unroll
    for (int i = 0; i < 6; i++) {
        int c4 = lane + i * 32;
        float4 wv = ((const float4*)w)[c4];
        float4 bv = ((const float4*)b)[c4];
        float y0 = (v[i].x - mean) * inv * wv.x + bv.x;
        float y1 = (v[i].y - mean) * inv * wv.y + bv.y;
        float y2 = (v[i].z - mean) * inv * wv.z + bv.z;
        float y3 = (v[i].w - mean) * inv * wv.w + bv.w;
        ((uint2*)ohi)[base4 + c4] = make_uint2(pack_h2(y0, y1), pack_h2(y2, y3));
    }
}

/* ------------------------------------------------------------------ */
/* silu(g)*u then LN over HIDDEN — WARP PER TOKEN (8 tokens/block)     */
/* ------------------------------------------------------------------ */
__global__ void __launch_bounds__(256) mlp_act_ln_kernel(
    const float* __restrict__ gu,
    const float* __restrict__ w, const float* __restrict__ b,
    __half* __restrict__ ohi) {
    int wid = threadIdx.x >> 5, lane = threadIdx.x & 31;
    int t = blockIdx.x * 8 + wid;
    const float* gr = gu + (size_t)t * GUS;
    const float* ur = gr + HIDDEN;
    float a[64];
    float s = 0.f, s2 = 0.f;
    #pragma unroll
    for (int i = 0; i < 16; i++) {
        int c4 = lane + i * 32;
        float4 gv = ((const float4*)gr)[c4];
        float4 uv = ((const float4*)ur)[c4];
        float* aj = a + i * 4;
        aj[0] = gv.x / (1.f + __expf(-gv.x)) * uv.x;
        aj[1] = gv.y / (1.f + __expf(-gv.y)) * uv.y;
        aj[2] = gv.z / (1.f + __expf(-gv.z)) * uv.z;
        aj[3] = gv.w / (1.f + __expf(-gv.w)) * uv.w;
        s  += aj[0] + aj[1] + aj[2] + aj[3];
        s2 += aj[0]*aj[0] + aj[1]*aj[1] + aj[2]*aj[2] + aj[3]*aj[3];
    }
    #pragma unroll
    for (int o = 16; o > 0; o >>= 1) {
        s  += __shfl_xor_sync(0xffffffffu, s,  o);
        s2 += __shfl_xor_sync(0xffffffffu, s2, o);
    }
    float mean = s / HIDDEN;
    float var  = s2 / HIDDEN - mean * mean;
    float inv  = rsqrtf(var + EPSF);
    #pragma unroll
    for (int i = 0; i < 16; i++) {
        int c4 = lane + i * 32;
        float4 wv = ((const float4*)w)[c4];
        float4 bv = ((const float4*)b)[c4];
        float* aj = a + i * 4;
        float y0 = (aj[0] - mean) * inv * wv.x + bv.x;
        float y1 = (aj[1] - mean) * inv * wv.y + bv.y;
        float y2 = (aj[2] - mean) * inv * wv.z + bv.z;
        float y3 = (aj[3] - mean) * inv * wv.w + bv.w;
        ((uint2*)ohi)[(size_t)t * (HIDDEN/4) + c4] =
            make_uint2(pack_h2(y0, y1), pack_h2(y2, y3));
    }
}

/* ------------------------------------------------------------------ */
/* Attention: 2 queries/thread, quad-strided slices, static max bound, */
/* packed f32x2 FMA inner loop.                                        */
/* ------------------------------------------------------------------ */
#define KVT 128
#define ATTN_SMEM (2*KVT*HD*4)    /* 65536 */
__global__ void __launch_bounds__(256) attn_kernel(
    const float* __restrict__ qkv, __half* __restrict__ ohi) {
    extern __shared__ float sm[];
    float* Ks = sm;
    float* Vs = sm + KVT * HD;
    int blk = blockIdx.x;
    int half_blk = blk & 1;
    int bh = blk >> 1;
    int b  = bh / HEADS, h = bh % HEADS;
    size_t base = (size_t)(b * NTOK) * QS + h * HD;
    int tid = threadIdx.x;
    int g  = tid & 3;
    int qb = tid >> 2;
    const float scale = 0.125f;

    float km2 = 0.f;
    {
        const float* kp = qkv + base + (size_t)tid * QS + DIM;
        #pragma unroll 4
        for (int c4 = 0; c4 < 16; c4++) {
            float4 t = *(const float4*)(kp + c4 * 4);
            km2 += t.x*t.x + t.y*t.y + t.z*t.z + t.w*t.w;
        }
    }
    float kmax = sqrtf(block_reduce_max(km2));

    u64t q2[2][8], acc2[2][8];
    float lrun[2], Mq[2];
    const u64t scale2 = pack2(scale, scale);
    #pragma unroll
    for (int r = 0; r < 2; r++) {
        int q = half_blk * 128 + qb + 64 * r;
        const float* qp = qkv + base + (size_t)q * QS;
        float qn2 = 0.f;
        #pragma unroll
        for (int k4 = 0; k4 < 4; k4++) {
            ulonglong2 v = *(const ulonglong2*)(qp + k4 * 16 + g * 4);
            q2[r][k4*2]   = mul2(v.x, scale2);
            q2[r][k4*2+1] = mul2(v.y, scale2);
            float2 a = unpack2(q2[r][k4*2]),  bb = unpack2(q2[r][k4*2+1]);
            qn2 += a.x*a.x + a.y*a.y + bb.x*bb.x + bb.y*bb.y;
        }
        qn2 += __shfl_xor_sync(0xffffffffu, qn2, 1);
        qn2 += __shfl_xor_sync(0xffffffffu, qn2, 2);
        Mq[r] = sqrtf(qn2) * kmax;
        lrun[r] = 0.f;
        #pragma unroll
        for (int d = 0; d < 8; d++) acc2[r][d] = 0ull;
    }

    for (int tkv = 0; tkv < NTOK / KVT; tkv++) {
        for (int i4 = tid; i4 < KVT * HD / 4; i4 += 256) {
            int row = i4 >> 4, c4 = i4 & 15;
            size_t src = base + (size_t)(tkv * KVT + row) * QS;
            ((float4*)Ks)[i4] = *(const float4*)(qkv + src + DIM   + c4 * 4);
            ((float4*)Vs)[i4] = *(const float4*)(qkv + src + 2*DIM + c4 * 4);
        }
        __syncthreads();

        for (int j = 0; j < KVT; j++) {
            u64t k2[8], v2[8];
            const float* kr = Ks + j * HD;
            const float* vr = Vs + j * HD;
            #pragma unroll
            for (int k4 = 0; k4 < 4; k4++) {
                ulonglong2 t = *(const ulonglong2*)(kr + k4 * 16 + g * 4);
                k2[k4*2] = t.x; k2[k4*2+1] = t.y;
                ulonglong2 u = *(const ulonglong2*)(vr + k4 * 16 + g * 4);
                v2[k4*2] = u.x; v2[k4*2+1] = u.y;
            }
            #pragma unroll
            for (int r = 0; r < 2; r++) {
                u64t d2 = 0ull;
                #pragma unroll
                for (int d = 0; d < 8; d++) d2 = fma2(q2[r][d], k2[d], d2);
                float2 dp = unpack2(d2);
                float s = dp.x + dp.y;
                s += __shfl_xor_sync(0xffffffffu, s, 1);
                s += __shfl_xor_sync(0xffffffffu, s, 2);
                float p = __expf(s - Mq[r]);
                lrun[r] += p;
                u64t p2 = pack2(p, p);
                #pragma unroll
                for (int d = 0; d < 8; d++)
                    acc2[r][d] = fma2(p2, v2[d], acc2[r][d]);
            }
        }
        __syncthreads();
    }

    #pragma unroll
    for (int r = 0; r < 2; r++) {
        float inv = 1.f / lrun[r];
        int q = half_blk * 128 + qb + 64 * r;
        size_t ob = (size_t)(b * NTOK + q) * DIM + h * HD;
        #pragma unroll
        for (int k4 = 0; k4 < 4; k4++) {
            float2 a = unpack2(acc2[r][k4*2]);
            float2 bb = unpack2(acc2[r][k4*2+1]);
            float y0 = a.x * inv,  y1 = a.y * inv;
            float y2 = bb.x * inv, y3 = bb.y * inv;
            *(uint2*)(ohi + ob + k4 * 16 + g * 4) =
                make_uint2(pack_h2(y0, y1), pack_h2(y2, y3));
        }
    }
}

/* ------------------------------------------------------------------ */
/* Launch                                                              */
/* ------------------------------------------------------------------ */
extern "C" void kernel_launch(void* const* d_in, const int* in_sizes, int n_in,
                              void* d_out, int out_size) {
    const float* x      = (const float*)d_in[0];
    const float* pos    = (const float*)d_in[1];
    const float* rope   = (const float*)d_in[2];
    const float* ln1_w  = (const float*)d_in[3];
    const float* ln1_b  = (const float*)d_in[4];
    const float* wq     = (const float*)d_in[5];
    const float* bq     = (const float*)d_in[6];
    const float* wk     = (const float*)d_in[7];
    const float* wv     = (const float*)d_in[8];
    const float* bv     = (const float*)d_in[9];
    const float* wo     = (const float*)d_in[10];
    const float* bo     = (const float*)d_in[11];
    const float* ln2_w  = (const float*)d_in[12];
    const float* ln2_b  = (const float*)d_in[13];
    const float* w1g    = (const float*)d_in[14];
    const float* b1g    = (const float*)d_in[15];
    const float* w1x    = (const float*)d_in[16];
    const float* b1x    = (const float*)d_in[17];
    const float* lnm_w  = (const float*)d_in[18];
    const float* lnm_b  = (const float*)d_in[19];
    const float* w2     = (const float*)d_in[20];
    const float* b2     = (const float*)d_in[21];
    float* h = (float*)d_out;

    float *qkv, *gu, *bqkv, *b1, *part;
    __half *yhh, *ohh, *mhh;
    __half *wqkvh, *wqkvl, *woh, *wol, *w1h, *w1l, *w2h, *w2l;
    cudaGetSymbolAddress((void**)&qkv,   g_qkv);
    cudaGetSymbolAddress((void**)&gu,    g_gu);
    cudaGetSymbolAddress((void**)&part,  g_part);
    cudaGetSymbolAddress((void**)&bqkv,  g_bqkv);
    cudaGetSymbolAddress((void**)&b1,    g_b1);
    cudaGetSymbolAddress((void**)&yhh,   g_yh_hi);
    cudaGetSymbolAddress((void**)&ohh,   g_oh_hi);
    cudaGetSymbolAddress((void**)&mhh,   g_mh_hi);
    cudaGetSymbolAddress((void**)&wqkvh, g_wqkv_hi);
    cudaGetSymbolAddress((void**)&wqkvl, g_wqkv_lo);
    cudaGetSymbolAddress((void**)&woh,   g_wo_hi);
    cudaGetSymbolAddress((void**)&wol,   g_wo_lo);
    cudaGetSymbolAddress((void**)&w1h,   g_w1_hi);
    cudaGetSymbolAddress((void**)&w1l,   g_w1_lo);
    cudaGetSymbolAddress((void**)&w2h,   g_w2_hi);
    cudaGetSymbolAddress((void**)&w2l,   g_w2_lo);

    cudaFuncSetAttribute((const void*)gemm_mma<true,false>,
                         cudaFuncAttributeMaxDynamicSharedMemorySize, GEMM_SMEM);
    cudaFuncSetAttribute((const void*)gemm_mma<false,false>,
                         cudaFuncAttributeMaxDynamicSharedMemorySize, GEMM_SMEM);
    cudaFuncSetAttribute((const void*)gemm_mma<false,true>,
                         cudaFuncAttributeMaxDynamicSharedMemorySize, GEMM_SMEM);
    cudaFuncSetAttribute((const void*)attn_kernel,
                         cudaFuncAttributeMaxDynamicSharedMemorySize, ATTN_SMEM);

    /* ---- [1] fused weight split + pack ---- */
    {
        const int nD = DIM*DIM, nH = HIDDEN*DIM;
        CvtArgs a;
        const float* srcs[7] = { wq, wk, wv, wo, w1g, w1x, w2 };
        __half* his[7] = { wqkvh, wqkvh, wqkvh, woh, w1h, w1h, w2h };
        __half* los[7] = { wqkvl, wqkvl, wqkvl, wol, w1l, w1l, w2l };
        int lrs[7]   = { nD, nD, nD, nD, nH, nH, nH };
        int ltots[7] = { QS*DIM, QS*DIM, QS*DIM, nD, GUS*DIM, GUS*DIM, nH };
        int offs[7]  = { 0, nD, 2*nD, 0, 0, nH, 0 };
        int cum = 0;
        for (int s = 0; s < 7; s++) {
            a.src[s] = srcs[s]; a.hi[s] = his[s]; a.lo[s] = los[s];
            a.lr[s] = lrs[s]; a.ltot[s] = ltots[s]; a.off[s] = offs[s];
            a.cum[s] = cum;
            cum += DEPTH * lrs[s] / 4;
        }
        a.cum[7] = cum;
        cvt_all<<<(cum + 255)/256, 256>>>(a, cum);
    }
    /* ---- [2] pos-embed add + bias packing ---- */
    add_pos_prep<<<(TOKENS*DIM + 255)/256, 256>>>(x, pos, h, bq, bv, bqkv,
                                                  b1g, b1x, b1);

    dim3 gQKV(QS/256,  TOKENS/128);      /* (9, 32)    */
    dim3 gMLP(GUS/256, TOKENS/128);      /* (16, 32)   */
    dim3 gSK (DIM/256, TOKENS/128, 3);   /* (3, 32, 3) */
    const int RED = (TOKENS*DIM/4 + 255)/256;
    const int LNG = TOKENS / 8;          /* warp-per-token grids */

    for (int l = 0; l < DEPTH; l++) {
        size_t oqkv = (size_t)l * QS * DIM;
        size_t owo  = (size_t)l * DIM * DIM;
        size_t ow1  = (size_t)l * GUS * DIM;
        size_t ow2  = (size_t)l * DIM * HIDDEN;

        /* ---- attention (ln1 fused with previous layer's W2 reduce) ---- */
        ln_fused<<<LNG, 256>>>(h,
            l == 0 ? nullptr : part,
            l == 0 ? nullptr : b2 + (l-1)*DIM,
            ln1_w + l*DIM, ln1_b + l*DIM, yhh);
        gemm_mma<true,false><<<gQKV, 256, GEMM_SMEM>>>(
            yhh, wqkvh + oqkv, wqkvl + oqkv,
            bqkv + l*QS, nullptr, qkv, rope, TOKENS, QS, DIM);
        attn_kernel<<<BATCH*HEADS*2, 256, ATTN_SMEM>>>(qkv, ohh);
        gemm_mma<false,true><<<gSK, 256, GEMM_SMEM>>>(
            ohh, woh + owo, wol + owo,
            nullptr, nullptr, part, nullptr, TOKENS, DIM, DIM);

        /* ---- SwiGLU MLP (ln2 fused with O-proj reduce) ---- */
        ln_fused<<<LNG, 256>>>(h, part, bo + l*DIM,
            ln2_w + l*DIM, ln2_b + l*DIM, yhh);
        gemm_mma<false,false><<<gMLP, 256, GEMM_SMEM>>>(
            yhh, w1h + ow1, w1l + ow1,
            b1 + l*GUS, nullptr, gu, nullptr, TOKENS, GUS, DIM);
        mlp_act_ln_kernel<<<LNG, 256>>>(gu, lnm_w + l*HIDDEN, lnm_b + l*HIDDEN, mhh);
        gemm_mma<false,true><<<gSK, 256, GEMM_SMEM>>>(
            mhh, w2h + ow2, w2l + ow2,
            nullptr, nullptr, part, nullptr, TOKENS, DIM, HIDDEN);
    }
    /* final residual reduce */
    reduce3<<<RED, 256>>>(h, part, b2 + (DEPTH-1)*DIM);
}